// round 15
// baseline (speedup 1.0000x reference)
#include <cuda_runtime.h>
#include <cuda_fp16.h>
#include <math.h>
#include <stdint.h>

// Problem constants
#define B_ 4
#define V_ 4
#define N_ 1000
#define INF_ 64
#define HEADS_ 4
#define D_ 128
#define E_ 64000
#define NTOT 4000
#define ETOT 68000
#define BVN 16000
#define NEG_SLOPE 0.2f
#define VSTRIDE (N_ * D_)
#define MAXDEG 64

// ---------------- scratch (static device globals; no allocation) -------------
// g_ss/g_sd rely on zero-init of device globals (nodes >= 1000 never written).
// g_cnt is re-zeroed by gather_kernel after each use.
// ORDERING: g_h is (b,v,n)-ordered; g_ghi/g_glo and g_qkv are (b,n,v)-ordered:
// row = 4*node + v, node = b*1000+n.
__device__ float g_h[BVN * D_];          // gemm1 out (fp32)
__device__ float g_qkv[BVN * 384];       // QKV out (fp32)
__device__ __half g_iwhi[384 * D_];      // in_w fp16
__device__ __half g_owhi[D_ * D_];       // out_w fp16
__device__ __half g_ghi[BVN * D_], g_glo[BVN * D_];    // hgat fp16 hi/lo
__device__ float g_ss[NTOT * HEADS_], g_sd[NTOT * HEADS_];
__device__ int   g_cnt[NTOT];
__device__ int   g_bsrc[NTOT * MAXDEG];

// ---------------- helpers ----------------------------------------------------
__device__ __forceinline__ uint32_t smem_u32(const void* p) {
    uint32_t a;
    asm("{ .reg .u64 t; cvta.to.shared.u64 t, %1; cvt.u32.u64 %0, t; }" : "=r"(a) : "l"(p));
    return a;
}
__device__ __forceinline__ void cpasync16(uint32_t s, const void* g) {
    asm volatile("cp.async.cg.shared.global [%0], [%1], 16;" :: "r"(s), "l"(g));
}
#define CP_COMMIT() asm volatile("cp.async.commit_group;" ::: "memory")
#define CP_WAIT0()  asm volatile("cp.async.wait_group 0;" ::: "memory")
#define LDSM4(r, addr) \
    asm volatile("ldmatrix.sync.aligned.m8n8.x4.shared.b16 {%0,%1,%2,%3}, [%4];" \
        : "=r"((r)[0]), "=r"((r)[1]), "=r"((r)[2]), "=r"((r)[3]) : "r"(addr))
#define MMA_FP16(d, a, b0v, b1v) \
    asm volatile("mma.sync.aligned.m16n8k16.row.col.f32.f16.f16.f32 " \
        "{%0,%1,%2,%3},{%4,%5,%6,%7},{%8,%9},{%0,%1,%2,%3};" \
        : "+f"((d)[0]), "+f"((d)[1]), "+f"((d)[2]), "+f"((d)[3]) \
        : "r"((a)[0]), "r"((a)[1]), "r"((a)[2]), "r"((a)[3]), "r"(b0v), "r"(b1v))

__device__ __forceinline__ void split_fp16(float v, __half* hi, __half* lo) {
    __half h = __float2half_rn(v);
    *hi = h;
    *lo = __float2half_rn(v - __half2float(h));
}
__device__ __forceinline__ uint32_t pack2h(__half a, __half b) {
    return (uint32_t)__half_as_ushort(a) | ((uint32_t)__half_as_ushort(b) << 16);
}

// =============== gemm1: h = x @ W^T (K=64), everything split in-kernel =======
// BM=64, BN=128, unpipelined, 3-pass fp16 (near-exact scores).
// grid = 296: 0..249 compute; 250..295 = edge buckets + iw/ow conversions.
#define G1_AS 9216     // 64 * 144
#define G1_BS 18432    // 128 * 144
__global__ __launch_bounds__(256, 2)
void gemm1_kernel(const float* __restrict__ x, const float* __restrict__ W,
                  const float* __restrict__ att, const int* __restrict__ ei,
                  const float* __restrict__ iw, const float* __restrict__ ow) {
    const int tid = threadIdx.x, lane = tid & 31, wid = tid >> 5;
    if (blockIdx.x >= 250) {
        int base = (blockIdx.x - 250) * 256 + tid;          // 0..11775
        for (int e = base; e < ETOT; e += 46 * 256) {
            int src, dst;
            if (e < E_) { src = ei[e]; dst = ei[E_ + e]; }
            else        { src = dst = e - E_; }
            int pos = atomicAdd(&g_cnt[dst], 1);
            if (pos < MAXDEG) g_bsrc[dst * MAXDEG + pos] = src;
        }
        for (int i = base; i < 384 * D_; i += 46 * 256) g_iwhi[i] = __float2half_rn(iw[i]);
        for (int i = base; i < D_ * D_; i += 46 * 256)  g_owhi[i] = __float2half_rn(ow[i]);
        return;
    }
    extern __shared__ char sm[];
    char* sAhi = sm;
    char* sAlo = sm + G1_AS;
    char* sBhi = sm + 2 * G1_AS;
    char* sBlo = sm + 2 * G1_AS + G1_BS;
    const int m0 = blockIdx.x * 64;
    const int warpM = wid & 3, warpN = wid >> 2;

    for (int c = tid; c < 1024; c += 256) {              // A: 64 rows * 16 float4
        int row = c >> 4, p = c & 15;
        float4 v = *(const float4*)(x + (size_t)(m0 + row) * 64 + p * 4);
        __half h0, l0, h1, l1, h2, l2, h3, l3;
        split_fp16(v.x, &h0, &l0); split_fp16(v.y, &h1, &l1);
        split_fp16(v.z, &h2, &l2); split_fp16(v.w, &h3, &l3);
        *(uint2*)(sAhi + row * 144 + p * 8) = make_uint2(pack2h(h0, h1), pack2h(h2, h3));
        *(uint2*)(sAlo + row * 144 + p * 8) = make_uint2(pack2h(l0, l1), pack2h(l2, l3));
    }
    for (int c = tid; c < 2048; c += 256) {              // B: 128 rows * 16 float4
        int row = c >> 4, p = c & 15;
        float4 v = *(const float4*)(W + (size_t)row * 64 + p * 4);
        __half h0, l0, h1, l1, h2, l2, h3, l3;
        split_fp16(v.x, &h0, &l0); split_fp16(v.y, &h1, &l1);
        split_fp16(v.z, &h2, &l2); split_fp16(v.w, &h3, &l3);
        *(uint2*)(sBhi + row * 144 + p * 8) = make_uint2(pack2h(h0, h1), pack2h(h2, h3));
        *(uint2*)(sBlo + row * 144 + p * 8) = make_uint2(pack2h(l0, l1), pack2h(l2, l3));
    }
    __syncthreads();

    uint32_t aoff = smem_u32(sAhi) + (warpM * 16 + (lane & 15)) * 144 + (lane >> 4) * 16;
    uint32_t boff[4];
#pragma unroll
    for (int j = 0; j < 4; j++)
        boff[j] = smem_u32(sBhi) + (warpN * 64 + j * 16 + (lane & 15)) * 144 + (lane >> 4) * 16;

    float acc[8][4];
#pragma unroll
    for (int f = 0; f < 8; f++)
#pragma unroll
        for (int j = 0; j < 4; j++) acc[f][j] = 0.0f;

#pragma unroll
    for (int kk = 0; kk < 4; kk++) {
        const uint32_t ko = kk * 32;
        uint32_t ar[4], brh[4][4], brl[4][4];
        LDSM4(ar, aoff + ko);
#pragma unroll
        for (int j = 0; j < 4; j++) LDSM4(brh[j], boff[j] + ko);
#pragma unroll
        for (int j = 0; j < 4; j++) LDSM4(brl[j], boff[j] + G1_BS + ko);
#pragma unroll
        for (int f = 0; f < 8; f++) {
            int j = f >> 1;
            MMA_FP16(acc[f], ar, (f & 1) ? brh[j][1] : brh[j][0], (f & 1) ? brh[j][3] : brh[j][2]);
        }
#pragma unroll
        for (int f = 0; f < 8; f++) {
            int j = f >> 1;
            MMA_FP16(acc[f], ar, (f & 1) ? brl[j][1] : brl[j][0], (f & 1) ? brl[j][3] : brl[j][2]);
        }
        LDSM4(ar, aoff + G1_AS + ko);
#pragma unroll
        for (int f = 0; f < 8; f++) {
            int j = f >> 1;
            MMA_FP16(acc[f], ar, (f & 1) ? brh[j][1] : brh[j][0], (f & 1) ? brh[j][3] : brh[j][2]);
        }
    }

    // fused GATv2 score halves for rows < 1000
    if (m0 < 1000) {
        int rl = m0 + warpM * 16 + (lane >> 2);
#pragma unroll
        for (int hh = 0; hh < 2; hh++) {
            int h = warpN * 2 + hh;
            float psl = 0.f, pdl = 0.f, psh = 0.f, pdh = 0.f;
#pragma unroll
            for (int q = 0; q < 4; q++) {
                int f = hh * 4 + q;
#pragma unroll
                for (int j = 0; j < 2; j++) {
                    int colw = q * 8 + 2 * (lane & 3) + j;
                    float wa = att[h * 64 + colw];
                    float wd = att[h * 64 + 32 + colw];
                    float vl = acc[f][j];
                    float ll = vl > 0.f ? vl : NEG_SLOPE * vl;
                    psl += wa * ll; pdl += wd * ll;
                    float vh = acc[f][2 + j];
                    float lh = vh > 0.f ? vh : NEG_SLOPE * vh;
                    psh += wa * lh; pdh += wd * lh;
                }
            }
            psl += __shfl_xor_sync(0xffffffffu, psl, 1);
            psl += __shfl_xor_sync(0xffffffffu, psl, 2);
            pdl += __shfl_xor_sync(0xffffffffu, pdl, 1);
            pdl += __shfl_xor_sync(0xffffffffu, pdl, 2);
            psh += __shfl_xor_sync(0xffffffffu, psh, 1);
            psh += __shfl_xor_sync(0xffffffffu, psh, 2);
            pdh += __shfl_xor_sync(0xffffffffu, pdh, 1);
            pdh += __shfl_xor_sync(0xffffffffu, pdh, 2);
            if ((lane & 3) == 0) {
                if (rl < 1000)     { g_ss[rl * 4 + h] = psl;       g_sd[rl * 4 + h] = pdl; }
                if (rl + 8 < 1000) { g_ss[(rl + 8) * 4 + h] = psh; g_sd[(rl + 8) * 4 + h] = pdh; }
            }
        }
    }

    // store h (fp32, (b,v,n) order)
    {
        int rl = m0 + warpM * 16 + (lane >> 2);
#pragma unroll
        for (int f = 0; f < 8; f++) {
            int c = warpN * 64 + f * 8 + 2 * (lane & 3);
            *(float2*)&g_h[(size_t)rl * D_ + c] = make_float2(acc[f][0], acc[f][1]);
            *(float2*)&g_h[(size_t)(rl + 8) * D_ + c] = make_float2(acc[f][2], acc[f][3]);
        }
    }
}

// shared tile geometry for the two K=128 GEMMs
#define RS   272
#define A_T  (64 * RS)            // 17408
#define B_T  (128 * RS)           // 34816
#define SMEM_G (2 * A_T + B_T)    // 69632

// =============== QKV GEMM: fp16 2-pass, K=128 single-shot ====================
__global__ __launch_bounds__(256, 3)
void mma_gemm(const __half* __restrict__ Ahi, const __half* __restrict__ Alo,
              const __half* __restrict__ Bhi,
              const float* __restrict__ bias1,
              float* __restrict__ C, int Nrow) {
    extern __shared__ char sm[];
    const int tid = threadIdx.x, lane = tid & 31, wid = tid >> 5;
    const int warpM = wid & 3, warpN = wid >> 2;
    const int m0 = blockIdx.x * 64, n0 = blockIdx.y * 128;

    {
        const uint32_t sb = smem_u32(sm);
#pragma unroll
        for (int i4 = 0; i4 < 4; i4++) {                 // A hi+lo
            int c = tid + i4 * 256;
            int row = c >> 4, chp = c & 15;
            uint32_t so = sb + row * RS + chp * 16;
            size_t ga = (size_t)(m0 + row) * D_ + chp * 8;
            cpasync16(so,       Ahi + ga);
            cpasync16(so + A_T, Alo + ga);
        }
#pragma unroll
        for (int i8 = 0; i8 < 8; i8++) {                 // B
            int c = tid + i8 * 256;
            int row = c >> 4, chp = c & 15;
            uint32_t so = sb + 2 * A_T + row * RS + chp * 16;
            size_t gb = (size_t)(n0 + row) * D_ + chp * 8;
            cpasync16(so, Bhi + gb);
        }
        CP_COMMIT();
    }

    uint32_t aoff = smem_u32(sm) + (warpM * 16 + (lane & 15)) * RS + (lane >> 4) * 16;
    uint32_t boff[4];
#pragma unroll
    for (int j = 0; j < 4; j++)
        boff[j] = smem_u32(sm) + 2 * A_T + (warpN * 64 + j * 16 + (lane & 15)) * RS
                  + (lane >> 4) * 16;

    float acc[8][4];
#pragma unroll
    for (int f = 0; f < 8; f++)
#pragma unroll
        for (int j = 0; j < 4; j++) acc[f][j] = 0.0f;

    CP_WAIT0();
    __syncthreads();

#pragma unroll
    for (int k16 = 0; k16 < 8; k16++) {
        const uint32_t ko = k16 * 32;
        uint32_t ar[4], br[4][4];
        LDSM4(ar, aoff + ko);
#pragma unroll
        for (int j = 0; j < 4; j++) LDSM4(br[j], boff[j] + ko);
#pragma unroll
        for (int f = 0; f < 8; f++) {
            int j = f >> 1;
            MMA_FP16(acc[f], ar, (f & 1) ? br[j][1] : br[j][0], (f & 1) ? br[j][3] : br[j][2]);
        }
        LDSM4(ar, aoff + A_T + ko);
#pragma unroll
        for (int f = 0; f < 8; f++) {
            int j = f >> 1;
            MMA_FP16(acc[f], ar, (f & 1) ? br[j][1] : br[j][0], (f & 1) ? br[j][3] : br[j][2]);
        }
    }

    int r1 = m0 + warpM * 16 + (lane >> 2);
    int r2 = r1 + 8;
#pragma unroll
    for (int f = 0; f < 8; f++) {
        int c = n0 + warpN * 64 + f * 8 + 2 * (lane & 3);
        float b0 = bias1 ? bias1[c] : 0.f;
        float b1 = bias1 ? bias1[c + 1] : 0.f;
        *(float2*)&C[(size_t)r1 * Nrow + c] = make_float2(acc[f][0] + b0, acc[f][1] + b1);
        *(float2*)&C[(size_t)r2 * Nrow + c] = make_float2(acc[f][2] + b0, acc[f][3] + b1);
    }
}

// =============== fused out-proj: MHA-over-V built in smem + GEMM + permute ===
// CTA covers 64 A-rows = 16 nodes. 8 warps run 8 (node,head) attention tasks
// each, writing fp16 hi/lo A directly to smem; then standard 2-pass GEMM
// against out_w; epilogue adds out_b+bias and un-permutes rows to (b,v,n).
__global__ __launch_bounds__(256, 3)
void outproj_kernel(const __half* __restrict__ Bhi,
                    const float* __restrict__ bias1, const float* __restrict__ bias2,
                    float* __restrict__ C) {
    extern __shared__ char sm[];
    const int tid = threadIdx.x, lane = tid & 31, wid = tid >> 5;
    const int warpM = wid & 3, warpN = wid >> 2;
    const int m0 = blockIdx.x * 64;
    const int node0 = blockIdx.x * 16;

    // start B (out_w) cp.async immediately
    {
        const uint32_t sb = smem_u32(sm) + 2 * A_T;
#pragma unroll
        for (int i8 = 0; i8 < 8; i8++) {
            int c = tid + i8 * 256;
            int row = c >> 4, chp = c & 15;
            cpasync16(sb + row * RS + chp * 16, Bhi + (size_t)row * D_ + chp * 8);
        }
        CP_COMMIT();
    }

    // attention for 16 nodes x 4 heads; warp handles tasks wid, wid+8, ...
    {
        char* sAhi = sm;
        char* sAlo = sm + A_T;
        const float scale = 0.17677669529663687f;  // 1/sqrt(32)
#pragma unroll
        for (int t = 0; t < 8; t++) {
            int task = wid + t * 8;
            int nl = task >> 2, h = task & 3;
            const float* base = g_qkv + (size_t)(4 * (node0 + nl)) * 384 + h * 32 + lane;
            float q[4], k[4], v[4];
#pragma unroll
            for (int i = 0; i < 4; i++) {
                q[i] = base[i * 384];
                k[i] = base[i * 384 + 128];
                v[i] = base[i * 384 + 256];
            }
            float s[4][4];
#pragma unroll
            for (int i = 0; i < 4; i++)
#pragma unroll
                for (int j = 0; j < 4; j++) {
                    float p = q[i] * k[j];
                    p += __shfl_xor_sync(0xffffffffu, p, 16);
                    p += __shfl_xor_sync(0xffffffffu, p, 8);
                    p += __shfl_xor_sync(0xffffffffu, p, 4);
                    p += __shfl_xor_sync(0xffffffffu, p, 2);
                    p += __shfl_xor_sync(0xffffffffu, p, 1);
                    s[i][j] = p * scale;
                }
#pragma unroll
            for (int i = 0; i < 4; i++) {
                float m = fmaxf(fmaxf(s[i][0], s[i][1]), fmaxf(s[i][2], s[i][3]));
                float e0 = __expf(s[i][0] - m), e1 = __expf(s[i][1] - m);
                float e2 = __expf(s[i][2] - m), e3 = __expf(s[i][3] - m);
                float inv = 1.0f / (e0 + e1 + e2 + e3);
                float o = (e0 * v[0] + e1 * v[1] + e2 * v[2] + e3 * v[3]) * inv;
                __half oh, ol;
                split_fp16(o, &oh, &ol);
                int off = (4 * nl + i) * RS + (h * 32 + lane) * 2;
                *(__half*)(sAhi + off) = oh;
                *(__half*)(sAlo + off) = ol;
            }
        }
    }

    CP_WAIT0();
    __syncthreads();

    uint32_t aoff = smem_u32(sm) + (warpM * 16 + (lane & 15)) * RS + (lane >> 4) * 16;
    uint32_t boff[4];
#pragma unroll
    for (int j = 0; j < 4; j++)
        boff[j] = smem_u32(sm) + 2 * A_T + (warpN * 64 + j * 16 + (lane & 15)) * RS
                  + (lane >> 4) * 16;

    float acc[8][4];
#pragma unroll
    for (int f = 0; f < 8; f++)
#pragma unroll
        for (int j = 0; j < 4; j++) acc[f][j] = 0.0f;

#pragma unroll
    for (int k16 = 0; k16 < 8; k16++) {
        const uint32_t ko = k16 * 32;
        uint32_t ar[4], br[4][4];
        LDSM4(ar, aoff + ko);
#pragma unroll
        for (int j = 0; j < 4; j++) LDSM4(br[j], boff[j] + ko);
#pragma unroll
        for (int f = 0; f < 8; f++) {
            int j = f >> 1;
            MMA_FP16(acc[f], ar, (f & 1) ? br[j][1] : br[j][0], (f & 1) ? br[j][3] : br[j][2]);
        }
        LDSM4(ar, aoff + A_T + ko);
#pragma unroll
        for (int f = 0; f < 8; f++) {
            int j = f >> 1;
            MMA_FP16(acc[f], ar, (f & 1) ? br[j][1] : br[j][0], (f & 1) ? br[j][3] : br[j][2]);
        }
    }

    // store with out_b + bias, un-permute rows (b,n,v) -> (b,v,n)
    int r1 = m0 + warpM * 16 + (lane >> 2);
    int r2 = r1 + 8;
    int bb = r1 / 4000, rr = r1 - bb * 4000;
    int or1 = bb * 4000 + (rr & 3) * 1000 + (rr >> 2);
    bb = r2 / 4000; rr = r2 - bb * 4000;
    int or2 = bb * 4000 + (rr & 3) * 1000 + (rr >> 2);
#pragma unroll
    for (int f = 0; f < 8; f++) {
        int c = warpN * 64 + f * 8 + 2 * (lane & 3);
        float b0 = bias1[c] + bias2[c];
        float b1 = bias1[c + 1] + bias2[c + 1];
        *(float2*)&C[(size_t)or1 * D_ + c] = make_float2(acc[f][0] + b0, acc[f][1] + b1);
        *(float2*)&C[(size_t)or2 * D_ + c] = make_float2(acc[f][2] + b0, acc[f][3] + b1);
    }
}

// ---------------- gather: denominator + aggregation -> fp16 split (b,n,v) ----
__global__ __launch_bounds__(128)
void gather_kernel() {
    __shared__ int ssrc[MAXDEG];
    int dst = blockIdx.x;            // 0..3999 == b*1000 + dl
    int b = dst / N_;
    int tid = threadIdx.x;           // feature 0..127
    int h = tid >> 5;
    int cnt = min(g_cnt[dst], MAXDEG);
    if (tid < cnt) ssrc[tid] = g_bsrc[dst * MAXDEG + tid];
    __syncthreads();
    if (tid == 0) g_cnt[dst] = 0;    // reset for next replay
    float sdh = g_sd[dst * 4 + h];
    float den = 0.f;
    float acc0 = 0.f, acc1 = 0.f, acc2 = 0.f, acc3 = 0.f;
    const float* hbase = g_h + (size_t)(b * V_) * VSTRIDE + tid;
#pragma unroll 2
    for (int i = 0; i < cnt; i++) {
        int src = ssrc[i];
        float ex = __expf(g_ss[src * 4 + h] + sdh);
        den += ex;
        if (src / N_ == b) {
            const float* hp = hbase + (size_t)(src - b * N_) * D_;
            acc0 += ex * hp[0];
            acc1 += ex * hp[VSTRIDE];
            acc2 += ex * hp[2 * VSTRIDE];
            acc3 += ex * hp[3 * VSTRIDE];
        }
    }
    float inv = 1.0f / (den + 1e-16f);
    size_t ob = (size_t)dst * 4 * D_ + tid;   // row = 4*dst + v, (b,n,v) order
    split_fp16(acc0 * inv, &g_ghi[ob],            &g_glo[ob]);
    split_fp16(acc1 * inv, &g_ghi[ob + D_],       &g_glo[ob + D_]);
    split_fp16(acc2 * inv, &g_ghi[ob + 2 * D_],   &g_glo[ob + 2 * D_]);
    split_fp16(acc3 * inv, &g_ghi[ob + 3 * D_],   &g_glo[ob + 3 * D_]);
}

// ---------------- launch -----------------------------------------------------
extern "C" void kernel_launch(void* const* d_in, const int* in_sizes, int n_in,
                              void* d_out, int out_size) {
    const float* x     = (const float*)d_in[0];     // [4,4,1000,64]
    const float* W     = (const float*)d_in[1];     // [128,64]
    const float* att   = (const float*)d_in[2];     // [1,4,64]
    const float* in_w  = (const float*)d_in[3];     // [384,128]
    const float* in_b  = (const float*)d_in[4];     // [384]
    const float* out_w = (const float*)d_in[5];     // [128,128]
    const float* out_b = (const float*)d_in[6];     // [128]
    const float* bias  = (const float*)d_in[7];     // [128]
    const int*   ei    = (const int*)d_in[8];       // [2,64000] int32
    float* out = (float*)d_out;                     // [4,4,1000,128]

    const int SMEM_1 = 2 * G1_AS + 2 * G1_BS;       // 55296
    cudaFuncSetAttribute(mma_gemm, cudaFuncAttributeMaxDynamicSharedMemorySize, SMEM_G);
    cudaFuncSetAttribute(outproj_kernel, cudaFuncAttributeMaxDynamicSharedMemorySize, SMEM_G);
    cudaFuncSetAttribute(gemm1_kernel, cudaFuncAttributeMaxDynamicSharedMemorySize, SMEM_1);

    void* p;
    cudaGetSymbolAddress(&p, g_qkv);   float* gqkv = (float*)p;
    cudaGetSymbolAddress(&p, g_iwhi);  __half* iwhi = (__half*)p;
    cudaGetSymbolAddress(&p, g_owhi);  __half* owhi = (__half*)p;
    cudaGetSymbolAddress(&p, g_ghi);   __half* ghi = (__half*)p;
    cudaGetSymbolAddress(&p, g_glo);   __half* glo = (__half*)p;

    // 1. gemm1: h = x @ W^T + fused scores; blocks 250.. = buckets + iw/ow conv
    gemm1_kernel<<<296, 256, SMEM_1>>>(x, W, att, ei, in_w, out_w);
    // 2. gather -> hgat fp16 split, (b,n,v) order (+cnt reset)
    gather_kernel<<<NTOT, 128>>>();
    // 3. QKV: hgat @ in_w^T + in_b ((b,n,v) rows)
    mma_gemm<<<dim3(250, 3), 256, SMEM_G>>>(ghi, glo, iwhi, in_b, gqkv, 384);
    // 4. fused MHA + out proj + out_b + bias + un-permute -> final output
    outproj_kernel<<<250, 256, SMEM_G>>>(owhi, out_b, bias, out);
}

// round 17
// speedup vs baseline: 1.4831x; 1.4831x over previous
#include <cuda_runtime.h>
#include <cuda_fp16.h>
#include <math.h>
#include <stdint.h>

// Problem constants
#define B_ 4
#define V_ 4
#define N_ 1000
#define INF_ 64
#define HEADS_ 4
#define D_ 128
#define E_ 64000
#define NTOT 4000
#define ETOT 68000
#define BVN 16000
#define NEG_SLOPE 0.2f
#define VSTRIDE (N_ * D_)
#define MAXDEG 64

// ---------------- scratch (static device globals; no allocation) -------------
// g_ss/g_sd rely on zero-init of device globals (nodes >= 1000 never written).
// g_cnt is re-zeroed by gather_kernel after each use.
// ORDERING: g_h is (b,v,n)-ordered; g_ghi/g_glo, g_qkv, g_aohi/g_aolo are
// (b,n,v)-ordered: row = 4*node + v, node = b*1000+n.
__device__ float g_h[BVN * D_];          // gemm1 out (fp32)
__device__ float g_qkv[BVN * 384];       // QKV out (fp32)
__device__ __half g_iwhi[384 * D_];      // in_w fp16
__device__ __half g_owhi[D_ * D_];       // out_w fp16
__device__ __half g_ghi[BVN * D_], g_glo[BVN * D_];    // hgat fp16 hi/lo
__device__ __half g_aohi[BVN * D_], g_aolo[BVN * D_];  // attn-out fp16 hi/lo
__device__ float g_ss[NTOT * HEADS_], g_sd[NTOT * HEADS_];
__device__ int   g_cnt[NTOT];
__device__ int   g_bsrc[NTOT * MAXDEG];

// ---------------- helpers ----------------------------------------------------
__device__ __forceinline__ uint32_t smem_u32(const void* p) {
    uint32_t a;
    asm("{ .reg .u64 t; cvta.to.shared.u64 t, %1; cvt.u32.u64 %0, t; }" : "=r"(a) : "l"(p));
    return a;
}
__device__ __forceinline__ void cpasync16(uint32_t s, const void* g) {
    asm volatile("cp.async.cg.shared.global [%0], [%1], 16;" :: "r"(s), "l"(g));
}
#define CP_COMMIT() asm volatile("cp.async.commit_group;" ::: "memory")
#define CP_WAIT0()  asm volatile("cp.async.wait_group 0;" ::: "memory")
#define LDSM4(r, addr) \
    asm volatile("ldmatrix.sync.aligned.m8n8.x4.shared.b16 {%0,%1,%2,%3}, [%4];" \
        : "=r"((r)[0]), "=r"((r)[1]), "=r"((r)[2]), "=r"((r)[3]) : "r"(addr))
#define MMA_FP16(d, a, b0v, b1v) \
    asm volatile("mma.sync.aligned.m16n8k16.row.col.f32.f16.f16.f32 " \
        "{%0,%1,%2,%3},{%4,%5,%6,%7},{%8,%9},{%0,%1,%2,%3};" \
        : "+f"((d)[0]), "+f"((d)[1]), "+f"((d)[2]), "+f"((d)[3]) \
        : "r"((a)[0]), "r"((a)[1]), "r"((a)[2]), "r"((a)[3]), "r"(b0v), "r"(b1v))

__device__ __forceinline__ void split_fp16(float v, __half* hi, __half* lo) {
    __half h = __float2half_rn(v);
    *hi = h;
    *lo = __float2half_rn(v - __half2float(h));
}
__device__ __forceinline__ uint32_t pack2h(__half a, __half b) {
    return (uint32_t)__half_as_ushort(a) | ((uint32_t)__half_as_ushort(b) << 16);
}

// =============== gemm1: h = x @ W^T (K=64), everything split in-kernel =======
// BM=64, BN=128, unpipelined, 3-pass fp16 (near-exact scores).
// grid = 296: 0..249 compute; 250..295 = edge buckets + iw/ow conversions.
#define G1_AS 9216     // 64 * 144
#define G1_BS 18432    // 128 * 144
__global__ __launch_bounds__(256, 2)
void gemm1_kernel(const float* __restrict__ x, const float* __restrict__ W,
                  const float* __restrict__ att, const int* __restrict__ ei,
                  const float* __restrict__ iw, const float* __restrict__ ow) {
    const int tid = threadIdx.x, lane = tid & 31, wid = tid >> 5;
    if (blockIdx.x >= 250) {
        int base = (blockIdx.x - 250) * 256 + tid;          // 0..11775
        for (int e = base; e < ETOT; e += 46 * 256) {
            int src, dst;
            if (e < E_) { src = ei[e]; dst = ei[E_ + e]; }
            else        { src = dst = e - E_; }
            int pos = atomicAdd(&g_cnt[dst], 1);
            if (pos < MAXDEG) g_bsrc[dst * MAXDEG + pos] = src;
        }
        for (int i = base; i < 384 * D_; i += 46 * 256) g_iwhi[i] = __float2half_rn(iw[i]);
        for (int i = base; i < D_ * D_; i += 46 * 256)  g_owhi[i] = __float2half_rn(ow[i]);
        return;
    }
    extern __shared__ char sm[];
    char* sAhi = sm;
    char* sAlo = sm + G1_AS;
    char* sBhi = sm + 2 * G1_AS;
    char* sBlo = sm + 2 * G1_AS + G1_BS;
    const int m0 = blockIdx.x * 64;
    const int warpM = wid & 3, warpN = wid >> 2;

    for (int c = tid; c < 1024; c += 256) {              // A: 64 rows * 16 float4
        int row = c >> 4, p = c & 15;
        float4 v = *(const float4*)(x + (size_t)(m0 + row) * 64 + p * 4);
        __half h0, l0, h1, l1, h2, l2, h3, l3;
        split_fp16(v.x, &h0, &l0); split_fp16(v.y, &h1, &l1);
        split_fp16(v.z, &h2, &l2); split_fp16(v.w, &h3, &l3);
        *(uint2*)(sAhi + row * 144 + p * 8) = make_uint2(pack2h(h0, h1), pack2h(h2, h3));
        *(uint2*)(sAlo + row * 144 + p * 8) = make_uint2(pack2h(l0, l1), pack2h(l2, l3));
    }
    for (int c = tid; c < 2048; c += 256) {              // B: 128 rows * 16 float4
        int row = c >> 4, p = c & 15;
        float4 v = *(const float4*)(W + (size_t)row * 64 + p * 4);
        __half h0, l0, h1, l1, h2, l2, h3, l3;
        split_fp16(v.x, &h0, &l0); split_fp16(v.y, &h1, &l1);
        split_fp16(v.z, &h2, &l2); split_fp16(v.w, &h3, &l3);
        *(uint2*)(sBhi + row * 144 + p * 8) = make_uint2(pack2h(h0, h1), pack2h(h2, h3));
        *(uint2*)(sBlo + row * 144 + p * 8) = make_uint2(pack2h(l0, l1), pack2h(l2, l3));
    }
    __syncthreads();

    uint32_t aoff = smem_u32(sAhi) + (warpM * 16 + (lane & 15)) * 144 + (lane >> 4) * 16;
    uint32_t boff[4];
#pragma unroll
    for (int j = 0; j < 4; j++)
        boff[j] = smem_u32(sBhi) + (warpN * 64 + j * 16 + (lane & 15)) * 144 + (lane >> 4) * 16;

    float acc[8][4];
#pragma unroll
    for (int f = 0; f < 8; f++)
#pragma unroll
        for (int j = 0; j < 4; j++) acc[f][j] = 0.0f;

#pragma unroll
    for (int kk = 0; kk < 4; kk++) {
        const uint32_t ko = kk * 32;
        uint32_t ar[4], brh[4][4], brl[4][4];
        LDSM4(ar, aoff + ko);
#pragma unroll
        for (int j = 0; j < 4; j++) LDSM4(brh[j], boff[j] + ko);
#pragma unroll
        for (int j = 0; j < 4; j++) LDSM4(brl[j], boff[j] + G1_BS + ko);
#pragma unroll
        for (int f = 0; f < 8; f++) {
            int j = f >> 1;
            MMA_FP16(acc[f], ar, (f & 1) ? brh[j][1] : brh[j][0], (f & 1) ? brh[j][3] : brh[j][2]);
        }
#pragma unroll
        for (int f = 0; f < 8; f++) {
            int j = f >> 1;
            MMA_FP16(acc[f], ar, (f & 1) ? brl[j][1] : brl[j][0], (f & 1) ? brl[j][3] : brl[j][2]);
        }
        LDSM4(ar, aoff + G1_AS + ko);
#pragma unroll
        for (int f = 0; f < 8; f++) {
            int j = f >> 1;
            MMA_FP16(acc[f], ar, (f & 1) ? brh[j][1] : brh[j][0], (f & 1) ? brh[j][3] : brh[j][2]);
        }
    }

    // fused GATv2 score halves for rows < 1000
    if (m0 < 1000) {
        int rl = m0 + warpM * 16 + (lane >> 2);
#pragma unroll
        for (int hh = 0; hh < 2; hh++) {
            int h = warpN * 2 + hh;
            float psl = 0.f, pdl = 0.f, psh = 0.f, pdh = 0.f;
#pragma unroll
            for (int q = 0; q < 4; q++) {
                int f = hh * 4 + q;
#pragma unroll
                for (int j = 0; j < 2; j++) {
                    int colw = q * 8 + 2 * (lane & 3) + j;
                    float wa = att[h * 64 + colw];
                    float wd = att[h * 64 + 32 + colw];
                    float vl = acc[f][j];
                    float ll = vl > 0.f ? vl : NEG_SLOPE * vl;
                    psl += wa * ll; pdl += wd * ll;
                    float vh = acc[f][2 + j];
                    float lh = vh > 0.f ? vh : NEG_SLOPE * vh;
                    psh += wa * lh; pdh += wd * lh;
                }
            }
            psl += __shfl_xor_sync(0xffffffffu, psl, 1);
            psl += __shfl_xor_sync(0xffffffffu, psl, 2);
            pdl += __shfl_xor_sync(0xffffffffu, pdl, 1);
            pdl += __shfl_xor_sync(0xffffffffu, pdl, 2);
            psh += __shfl_xor_sync(0xffffffffu, psh, 1);
            psh += __shfl_xor_sync(0xffffffffu, psh, 2);
            pdh += __shfl_xor_sync(0xffffffffu, pdh, 1);
            pdh += __shfl_xor_sync(0xffffffffu, pdh, 2);
            if ((lane & 3) == 0) {
                if (rl < 1000)     { g_ss[rl * 4 + h] = psl;       g_sd[rl * 4 + h] = pdl; }
                if (rl + 8 < 1000) { g_ss[(rl + 8) * 4 + h] = psh; g_sd[(rl + 8) * 4 + h] = pdh; }
            }
        }
    }

    // store h (fp32, (b,v,n) order)
    {
        int rl = m0 + warpM * 16 + (lane >> 2);
#pragma unroll
        for (int f = 0; f < 8; f++) {
            int c = warpN * 64 + f * 8 + 2 * (lane & 3);
            *(float2*)&g_h[(size_t)rl * D_ + c] = make_float2(acc[f][0], acc[f][1]);
            *(float2*)&g_h[(size_t)(rl + 8) * D_ + c] = make_float2(acc[f][2], acc[f][3]);
        }
    }
}

// =============== fp16 2-pass MMA GEMM, K=128 single-shot =====================
// BM=64 BN=128; 8 warps 4m x 2n; warp tile 16x64; 3 CTAs/SM.
// perm != 0: un-permute rows (b,n,v) -> (b,v,n) at store (out-proj only).
#define RS   272
#define A_T  (64 * RS)            // 17408
#define B_T  (128 * RS)           // 34816
#define SMEM_G (2 * A_T + B_T)    // 69632
__global__ __launch_bounds__(256, 3)
void mma_gemm(const __half* __restrict__ Ahi, const __half* __restrict__ Alo,
              const __half* __restrict__ Bhi,
              const float* __restrict__ bias1, const float* __restrict__ bias2,
              float* __restrict__ C, int Nrow, int perm) {
    extern __shared__ char sm[];
    const int tid = threadIdx.x, lane = tid & 31, wid = tid >> 5;
    const int warpM = wid & 3, warpN = wid >> 2;
    const int m0 = blockIdx.x * 64, n0 = blockIdx.y * 128;

    {
        const uint32_t sb = smem_u32(sm);
#pragma unroll
        for (int i4 = 0; i4 < 4; i4++) {                 // A hi+lo
            int c = tid + i4 * 256;
            int row = c >> 4, chp = c & 15;
            uint32_t so = sb + row * RS + chp * 16;
            size_t ga = (size_t)(m0 + row) * D_ + chp * 8;
            cpasync16(so,       Ahi + ga);
            cpasync16(so + A_T, Alo + ga);
        }
#pragma unroll
        for (int i8 = 0; i8 < 8; i8++) {                 // B
            int c = tid + i8 * 256;
            int row = c >> 4, chp = c & 15;
            uint32_t so = sb + 2 * A_T + row * RS + chp * 16;
            size_t gb = (size_t)(n0 + row) * D_ + chp * 8;
            cpasync16(so, Bhi + gb);
        }
        CP_COMMIT();
    }

    uint32_t aoff = smem_u32(sm) + (warpM * 16 + (lane & 15)) * RS + (lane >> 4) * 16;
    uint32_t boff[4];
#pragma unroll
    for (int j = 0; j < 4; j++)
        boff[j] = smem_u32(sm) + 2 * A_T + (warpN * 64 + j * 16 + (lane & 15)) * RS
                  + (lane >> 4) * 16;

    float acc[8][4];
#pragma unroll
    for (int f = 0; f < 8; f++)
#pragma unroll
        for (int j = 0; j < 4; j++) acc[f][j] = 0.0f;

    CP_WAIT0();
    __syncthreads();

#pragma unroll
    for (int k16 = 0; k16 < 8; k16++) {
        const uint32_t ko = k16 * 32;
        uint32_t ar[4], br[4][4];
        LDSM4(ar, aoff + ko);
#pragma unroll
        for (int j = 0; j < 4; j++) LDSM4(br[j], boff[j] + ko);
#pragma unroll
        for (int f = 0; f < 8; f++) {
            int j = f >> 1;
            MMA_FP16(acc[f], ar, (f & 1) ? br[j][1] : br[j][0], (f & 1) ? br[j][3] : br[j][2]);
        }
        LDSM4(ar, aoff + A_T + ko);
#pragma unroll
        for (int f = 0; f < 8; f++) {
            int j = f >> 1;
            MMA_FP16(acc[f], ar, (f & 1) ? br[j][1] : br[j][0], (f & 1) ? br[j][3] : br[j][2]);
        }
    }

    // store with fused biases (+ optional (b,n,v)->(b,v,n) row un-permute)
    int r1 = m0 + warpM * 16 + (lane >> 2);
    int r2 = r1 + 8;
    int or1 = r1, or2 = r2;
    if (perm) {
        int bb = r1 / 4000, rr = r1 - bb * 4000;
        or1 = bb * 4000 + (rr & 3) * 1000 + (rr >> 2);
        bb = r2 / 4000; rr = r2 - bb * 4000;
        or2 = bb * 4000 + (rr & 3) * 1000 + (rr >> 2);
    }
#pragma unroll
    for (int f = 0; f < 8; f++) {
        int c = n0 + warpN * 64 + f * 8 + 2 * (lane & 3);
        float b0 = 0.f, b1 = 0.f;
        if (bias1) { b0 += bias1[c]; b1 += bias1[c + 1]; }
        if (bias2) { b0 += bias2[c]; b1 += bias2[c + 1]; }
        *(float2*)&C[(size_t)or1 * Nrow + c] = make_float2(acc[f][0] + b0, acc[f][1] + b1);
        *(float2*)&C[(size_t)or2 * Nrow + c] = make_float2(acc[f][2] + b0, acc[f][3] + b1);
    }
}

// ---------------- gather: denominator + aggregation -> fp16 split (b,n,v) ----
// Exps computed ONCE per (edge, head) into smem (strided loop covers 4*cnt
// entries with 128 threads — R16's bug was a single-shot guard).
__global__ __launch_bounds__(128)
void gather_kernel() {
    __shared__ int   ssrc[MAXDEG];
    __shared__ float sex[MAXDEG * 4];   // [edge][head]
    int dst = blockIdx.x;            // 0..3999 == b*1000 + dl
    int b = dst / N_;
    int tid = threadIdx.x;           // feature 0..127
    int h = tid >> 5;
    int cnt = min(g_cnt[dst], MAXDEG);
    if (tid < cnt) ssrc[tid] = g_bsrc[dst * MAXDEG + tid];
    __syncthreads();
    for (int t = tid; t < 4 * cnt; t += 128) {
        int i = t >> 2, hh = t & 3;
        sex[t] = __expf(g_ss[ssrc[i] * 4 + hh] + g_sd[dst * 4 + hh]);
    }
    __syncthreads();
    if (tid == 0) g_cnt[dst] = 0;    // reset for next replay
    float den = 0.f;
    float acc0 = 0.f, acc1 = 0.f, acc2 = 0.f, acc3 = 0.f;
    const float* hbase = g_h + (size_t)(b * V_) * VSTRIDE + tid;
#pragma unroll 2
    for (int i = 0; i < cnt; i++) {
        int src = ssrc[i];
        float ex = sex[i * 4 + h];             // broadcast LDS
        den += ex;
        if (src / N_ == b) {
            const float* hp = hbase + (size_t)(src - b * N_) * D_;
            acc0 += ex * hp[0];
            acc1 += ex * hp[VSTRIDE];
            acc2 += ex * hp[2 * VSTRIDE];
            acc3 += ex * hp[3 * VSTRIDE];
        }
    }
    float inv = 1.0f / (den + 1e-16f);
    size_t ob = (size_t)dst * 4 * D_ + tid;   // row = 4*dst + v, (b,n,v) order
    split_fp16(acc0 * inv, &g_ghi[ob],            &g_glo[ob]);
    split_fp16(acc1 * inv, &g_ghi[ob + D_],       &g_glo[ob + D_]);
    split_fp16(acc2 * inv, &g_ghi[ob + 2 * D_],   &g_glo[ob + 2 * D_]);
    split_fp16(acc3 * inv, &g_ghi[ob + 3 * D_],   &g_glo[ob + 3 * D_]);
}

// ---------------- per-(node,head) MHA over V, register-only ------------------
// warp = (node, head); qkv rows 4*node..4*node+3 are contiguous ((b,n,v) order).
__global__ __launch_bounds__(256)
void attn_kernel() {
    int wid = threadIdx.x >> 5, l = threadIdx.x & 31;
    int node = blockIdx.x * 2 + (wid >> 2);
    int h = wid & 3;
    const float* base = g_qkv + (size_t)(4 * node) * 384 + h * 32 + l;
    float q[4], k[4], v[4];
#pragma unroll
    for (int i = 0; i < 4; i++) {
        q[i] = base[i * 384];
        k[i] = base[i * 384 + 128];
        v[i] = base[i * 384 + 256];
    }
    const float scale = 0.17677669529663687f;  // 1/sqrt(32)
    float s[4][4];
#pragma unroll
    for (int i = 0; i < 4; i++)
#pragma unroll
        for (int j = 0; j < 4; j++) {
            float p = q[i] * k[j];
            p += __shfl_xor_sync(0xffffffffu, p, 16);
            p += __shfl_xor_sync(0xffffffffu, p, 8);
            p += __shfl_xor_sync(0xffffffffu, p, 4);
            p += __shfl_xor_sync(0xffffffffu, p, 2);
            p += __shfl_xor_sync(0xffffffffu, p, 1);
            s[i][j] = p * scale;
        }
#pragma unroll
    for (int i = 0; i < 4; i++) {
        float m = fmaxf(fmaxf(s[i][0], s[i][1]), fmaxf(s[i][2], s[i][3]));
        float e0 = __expf(s[i][0] - m), e1 = __expf(s[i][1] - m);
        float e2 = __expf(s[i][2] - m), e3 = __expf(s[i][3] - m);
        float inv = 1.0f / (e0 + e1 + e2 + e3);
        float o = (e0 * v[0] + e1 * v[1] + e2 * v[2] + e3 * v[3]) * inv;
        size_t idx = (size_t)(4 * node + i) * D_ + h * 32 + l;
        split_fp16(o, &g_aohi[idx], &g_aolo[idx]);
    }
}

// ---------------- launch -----------------------------------------------------
extern "C" void kernel_launch(void* const* d_in, const int* in_sizes, int n_in,
                              void* d_out, int out_size) {
    const float* x     = (const float*)d_in[0];     // [4,4,1000,64]
    const float* W     = (const float*)d_in[1];     // [128,64]
    const float* att   = (const float*)d_in[2];     // [1,4,64]
    const float* in_w  = (const float*)d_in[3];     // [384,128]
    const float* in_b  = (const float*)d_in[4];     // [384]
    const float* out_w = (const float*)d_in[5];     // [128,128]
    const float* out_b = (const float*)d_in[6];     // [128]
    const float* bias  = (const float*)d_in[7];     // [128]
    const int*   ei    = (const int*)d_in[8];       // [2,64000] int32
    float* out = (float*)d_out;                     // [4,4,1000,128]

    const int SMEM_1 = 2 * G1_AS + 2 * G1_BS;       // 55296
    cudaFuncSetAttribute(mma_gemm, cudaFuncAttributeMaxDynamicSharedMemorySize, SMEM_G);
    cudaFuncSetAttribute(gemm1_kernel, cudaFuncAttributeMaxDynamicSharedMemorySize, SMEM_1);

    void* p;
    cudaGetSymbolAddress(&p, g_qkv);   float* gqkv = (float*)p;
    cudaGetSymbolAddress(&p, g_iwhi);  __half* iwhi = (__half*)p;
    cudaGetSymbolAddress(&p, g_owhi);  __half* owhi = (__half*)p;
    cudaGetSymbolAddress(&p, g_ghi);   __half* ghi = (__half*)p;
    cudaGetSymbolAddress(&p, g_glo);   __half* glo = (__half*)p;
    cudaGetSymbolAddress(&p, g_aohi);  __half* aohi = (__half*)p;
    cudaGetSymbolAddress(&p, g_aolo);  __half* aolo = (__half*)p;

    // 1. gemm1: h = x @ W^T + fused scores; blocks 250.. = buckets + iw/ow conv
    gemm1_kernel<<<296, 256, SMEM_1>>>(x, W, att, ei, in_w, out_w);
    // 2. gather -> hgat fp16 split, (b,n,v) order (+cnt reset)
    gather_kernel<<<NTOT, 128>>>();
    // 3. QKV: hgat @ in_w^T + in_b ((b,n,v) rows, no permute)
    mma_gemm<<<dim3(250, 3), 256, SMEM_G>>>(ghi, glo, iwhi, in_b, nullptr,
                                            gqkv, 384, 0);
    // 4. MHA over V: register-only, contiguous qkv rows
    attn_kernel<<<2000, 256>>>();
    // 5. out proj + out_b + bias, un-permute rows -> final (b,v,n) output
    mma_gemm<<<dim3(250, 1), 256, SMEM_G>>>(aohi, aolo, owhi, out_b, bias,
                                            out, D_, 1);
}